// round 8
// baseline (speedup 1.0000x reference)
#include <cuda_runtime.h>
#include <cuda_bf16.h>

// ROI mean-pool, v8: register column-scan straight from global (no stage-in,
// no SMEM scan round-trip) + float4 thread-per-box evaluation with word masks.
//
// fmap:  [B=64, C=256, H=80, W=80] float32
// boxes: [B=64, N=100, 4] xyxy in [0,640]
// out:   [B, N, C] float32
//
// SMEM layout (column prefix C):
//   rows 1..40  (true prefix)   at S[(y-1)*80]   <- plane rows 0..39
//   rows 41..80 (LOCAL prefix)  at S[(y-1)*80]   <- plane rows 40..79
//   C_true[y>=41] = local + C[40];  C[40] = S[39*80].  C[0] = zrow.

#define Bn   64
#define Cn   256
#define Hn   80
#define Wn   80
#define Nn   100

__global__ __launch_bounds__(256)
void roi_pool_v8_kernel(const float* __restrict__ fmap,
                        const float* __restrict__ boxes,
                        float* __restrict__ out)
{
    __shared__ __align__(16) float S[Hn * Wn];     // 25,600 B
    __shared__ __align__(16) float zrow[Wn];
    __shared__ int4 BC[Nn];

    const int p   = blockIdx.x;            // plane id = b*Cn + c
    const int b   = p >> 8;
    const int c   = p & 255;
    const int tid = threadIdx.x;

    const float* __restrict__ plane = fmap + (size_t)p * (Hn * Wn);

    // ---- Phase 1 (single sync) -------------------------------------------
    if (tid < 40) {
        // Thread (seg, fc): columns 4*fc..4*fc+3, plane rows seg*40..+39.
        // Register scan: only the prefix is written to SMEM (STS.128).
        const int seg = tid / 20;
        const int fc  = tid % 20;
        const float4* __restrict__ g =
            reinterpret_cast<const float4*>(plane) + seg * 40 * 20 + fc;
        float4* __restrict__ d =
            reinterpret_cast<float4*>(S) + seg * 40 * 20 + fc;

        float4 acc = make_float4(0.f, 0.f, 0.f, 0.f);
        #pragma unroll 8
        for (int i = 0; i < 40; ++i) {
            float4 v = g[i * 20];          // independent LDG.128, pipelined
            acc.x += v.x; acc.y += v.y; acc.z += v.z; acc.w += v.w;
            d[i * 20] = acc;
        }
    } else if (tid >= 64 && tid < 64 + Nn) {
        // Box coords once per CTA (overlapped with the loads).
        const int n = tid - 64;
        float4 bb = reinterpret_cast<const float4*>(boxes + (size_t)b * (Nn * 4))[n];
        // Match JAX exactly: IEEE div by 640, IEEE mul by 80, trunc, clip.
        int x1 = min(max((int)(__fmul_rn(__fdiv_rn(bb.x, 640.0f), 80.0f)), 0), Wn);
        int y1 = min(max((int)(__fmul_rn(__fdiv_rn(bb.y, 640.0f), 80.0f)), 0), Hn);
        int x2 = min(max((int)(__fmul_rn(__fdiv_rn(bb.z, 640.0f), 80.0f)), 0), Wn);
        int y2 = min(max((int)(__fmul_rn(__fdiv_rn(bb.w, 640.0f), 80.0f)), 0), Hn);
        BC[n] = make_int4(x1, y1, x2, y2);
    } else if (tid >= 176) {
        zrow[tid - 176] = 0.0f;            // 80 threads
    }
    __syncthreads();

    // ---- Phase 2: thread-per-box, float4 LDS with word masking -----------
    if (tid < Nn) {
        int4 q = BC[tid];                  // x1,y1,x2,y2
        const float* __restrict__ r2 = (q.w > 0) ? S + (q.w - 1) * Wn : zrow;
        const float* __restrict__ r1 = (q.y > 0) ? S + (q.y - 1) * Wn : zrow;
        const float* __restrict__ tr = S + 39 * Wn;        // C[40]
        const bool straddle = (q.y <= 40) && (q.w >= 41);

        const unsigned width = (unsigned)(q.z - q.x);
        const int xa = q.x & ~3;           // 16B-aligned start
        float s = 0.0f;

        if (straddle) {
            for (int x4 = xa; x4 < q.z; x4 += 4) {
                float4 a  = *reinterpret_cast<const float4*>(r2 + x4);
                float4 bb = *reinterpret_cast<const float4*>(r1 + x4);
                float4 t  = *reinterpret_cast<const float4*>(tr + x4);
                if ((unsigned)(x4 + 0 - q.x) < width) s += a.x - bb.x + t.x;
                if ((unsigned)(x4 + 1 - q.x) < width) s += a.y - bb.y + t.y;
                if ((unsigned)(x4 + 2 - q.x) < width) s += a.z - bb.z + t.z;
                if ((unsigned)(x4 + 3 - q.x) < width) s += a.w - bb.w + t.w;
            }
        } else {
            for (int x4 = xa; x4 < q.z; x4 += 4) {
                float4 a  = *reinterpret_cast<const float4*>(r2 + x4);
                float4 bb = *reinterpret_cast<const float4*>(r1 + x4);
                if ((unsigned)(x4 + 0 - q.x) < width) s += a.x - bb.x;
                if ((unsigned)(x4 + 1 - q.x) < width) s += a.y - bb.y;
                if ((unsigned)(x4 + 2 - q.x) < width) s += a.z - bb.z;
                if ((unsigned)(x4 + 3 - q.x) < width) s += a.w - bb.w;
            }
        }

        int dy = q.w - q.y;
        int dx = q.z - q.x;
        bool valid = (dy > 0) && (dx > 0);
        int  area  = max(dy * dx, 1);

        out[(size_t)b * (Nn * Cn) + (size_t)tid * Cn + c] =
            valid ? s / (float)area : 0.0f;
    }
}

extern "C" void kernel_launch(void* const* d_in, const int* in_sizes, int n_in,
                              void* d_out, int out_size)
{
    const float* fmap  = (const float*)d_in[0];   // [64,256,80,80]
    const float* boxes = (const float*)d_in[1];   // [64,100,4]
    float*       out   = (float*)d_out;           // [64,100,256]

    (void)in_sizes; (void)n_in; (void)out_size;

    roi_pool_v8_kernel<<<Bn * Cn, 256>>>(fmap, boxes, out);
}

// round 9
// speedup vs baseline: 1.2703x; 1.2703x over previous
#include <cuda_runtime.h>
#include <cuda_bf16.h>

// ROI mean-pool, v9 = v3 + v8 hybrid:
//   all-thread float4 stage-in  (latency-robust, 400 wf)
//   160-thread split column scan (40-deep chains, ~400 wf)
//   thread-per-box masked float4 evaluation (~450 wf)
//
// fmap:  [B=64, C=256, H=80, W=80] float32
// boxes: [B=64, N=100, 4] xyxy in [0,640]
// out:   [B, N, C] float32
//
// SMEM column prefix C (in place over the plane):
//   rows 1..40  true prefix  at S[(y-1)*80]  <- plane rows 0..39
//   rows 41..80 LOCAL prefix at S[(y-1)*80]  <- plane rows 40..79
//   C_true[y>=41] = local + C[40];  C[40] = S[39*80].  C[0] = zrow.

#define Bn   64
#define Cn   256
#define Hn   80
#define Wn   80
#define Nn   100

__global__ __launch_bounds__(256)
void roi_pool_v9_kernel(const float* __restrict__ fmap,
                        const float* __restrict__ boxes,
                        float* __restrict__ out)
{
    __shared__ __align__(16) float S[Hn * Wn];     // 25,600 B
    __shared__ __align__(16) float zrow[Wn];
    __shared__ int4 BC[Nn];

    const int p   = blockIdx.x;            // plane id = b*Cn + c
    const int b   = p >> 8;
    const int c   = p & 255;
    const int tid = threadIdx.x;

    const float* __restrict__ plane = fmap + (size_t)p * (Hn * Wn);

    // ---- Phase 1a: coalesced float4 stage-in, ALL 256 threads ------------
    #pragma unroll
    for (int i = tid; i < (Hn * Wn) / 4; i += 256) {
        float4 v = reinterpret_cast<const float4*>(plane)[i];
        reinterpret_cast<float4*>(S)[i] = v;
    }

    // ---- Phase 1b (overlapped): box coords + zero row --------------------
    if (tid < Nn) {
        float4 bb = reinterpret_cast<const float4*>(boxes + (size_t)b * (Nn * 4))[tid];
        // Match JAX exactly: IEEE div by 640, IEEE mul by 80, trunc, clip.
        int x1 = min(max((int)(__fmul_rn(__fdiv_rn(bb.x, 640.0f), 80.0f)), 0), Wn);
        int y1 = min(max((int)(__fmul_rn(__fdiv_rn(bb.y, 640.0f), 80.0f)), 0), Hn);
        int x2 = min(max((int)(__fmul_rn(__fdiv_rn(bb.z, 640.0f), 80.0f)), 0), Wn);
        int y2 = min(max((int)(__fmul_rn(__fdiv_rn(bb.w, 640.0f), 80.0f)), 0), Hn);
        BC[tid] = make_int4(x1, y1, x2, y2);
    } else if (tid >= 128 && tid < 128 + Wn) {
        zrow[tid - 128] = 0.0f;
    }
    __syncthreads();

    // ---- Phase 2: split in-place column scan (160 threads, 40-deep) ------
    // Threads 0..79: column tid, rows 0..39 -> true prefix C[1..40].
    // Threads 80..159: column tid-80, rows 40..79 -> local prefix.
    if (tid < 160) {
        const int col  = (tid < Wn) ? tid : tid - Wn;
        const int rowb = (tid < Wn) ? 0 : 40;
        float* d = S + rowb * Wn + col;
        float acc = 0.0f;
        #pragma unroll 8
        for (int i = 0; i < 40; ++i) {
            acc += d[i * Wn];              // 160 consecutive lanes: conflict-free
            d[i * Wn] = acc;
        }
    }
    __syncthreads();

    // ---- Phase 3: thread-per-box, masked float4 LDS ----------------------
    if (tid < Nn) {
        int4 q = BC[tid];                  // x1,y1,x2,y2
        const float* __restrict__ r2 = (q.w > 0) ? S + (q.w - 1) * Wn : zrow;
        const float* __restrict__ r1 = (q.y > 0) ? S + (q.y - 1) * Wn : zrow;
        const float* __restrict__ tr = S + 39 * Wn;        // C[40]
        const bool straddle = (q.y <= 40) && (q.w >= 41);

        const unsigned width = (unsigned)(q.z - q.x);
        const int xa = q.x & ~3;           // rows are 320B, 16B aligned
        float s = 0.0f;

        if (straddle) {
            for (int x4 = xa; x4 < q.z; x4 += 4) {
                float4 a  = *reinterpret_cast<const float4*>(r2 + x4);
                float4 bb = *reinterpret_cast<const float4*>(r1 + x4);
                float4 t  = *reinterpret_cast<const float4*>(tr + x4);
                if ((unsigned)(x4 + 0 - q.x) < width) s += a.x - bb.x + t.x;
                if ((unsigned)(x4 + 1 - q.x) < width) s += a.y - bb.y + t.y;
                if ((unsigned)(x4 + 2 - q.x) < width) s += a.z - bb.z + t.z;
                if ((unsigned)(x4 + 3 - q.x) < width) s += a.w - bb.w + t.w;
            }
        } else {
            for (int x4 = xa; x4 < q.z; x4 += 4) {
                float4 a  = *reinterpret_cast<const float4*>(r2 + x4);
                float4 bb = *reinterpret_cast<const float4*>(r1 + x4);
                if ((unsigned)(x4 + 0 - q.x) < width) s += a.x - bb.x;
                if ((unsigned)(x4 + 1 - q.x) < width) s += a.y - bb.y;
                if ((unsigned)(x4 + 2 - q.x) < width) s += a.z - bb.z;
                if ((unsigned)(x4 + 3 - q.x) < width) s += a.w - bb.w;
            }
        }

        int dy = q.w - q.y;
        int dx = q.z - q.x;
        bool valid = (dy > 0) && (dx > 0);
        int  area  = max(dy * dx, 1);

        out[(size_t)b * (Nn * Cn) + (size_t)tid * Cn + c] =
            valid ? s / (float)area : 0.0f;
    }
}

extern "C" void kernel_launch(void* const* d_in, const int* in_sizes, int n_in,
                              void* d_out, int out_size)
{
    const float* fmap  = (const float*)d_in[0];   // [64,256,80,80]
    const float* boxes = (const float*)d_in[1];   // [64,100,4]
    float*       out   = (float*)d_out;           // [64,100,256]

    (void)in_sizes; (void)n_in; (void)out_size;

    roi_pool_v9_kernel<<<Bn * Cn, 256>>>(fmap, boxes, out);
}

// round 10
// speedup vs baseline: 1.3844x; 1.0898x over previous
#include <cuda_runtime.h>
#include <cuda_bf16.h>

// ROI mean-pool, v10: full 2D integral image with split scans, O(1) box reads.
//
// fmap:  [B=64, C=256, H=80, W=80] float32
// boxes: [B=64, N=100, 4] xyxy in [0,640]
// out:   [B, N, C] float32
//
// SMEM M[80][81] (stride 81, odd -> all phases conflict-free):
//   After col scan:  M[r][x] = col prefix; rows r<40 true C[r+1], r>=40 LOCAL.
//   After row scan:  M[r][x] = x-prefix within half (x<40 | x>=40) of the above.
// True 2D integral g(y,x) = S2D[y][x] reconstructed per corner:
//   r=y-1, xi=x-1:  g = M[r][xi]
//                     + (xi>=40 ? M[r][39]  : 0)        // x-half stitch
//                     + (y>=41  ? M[39][xi] + (xi>=40 ? M[39][39] : 0) : 0) // y stitch
// Box sum = g(y2,x2) - g(y1,x2) - g(y2,x1) + g(y1,x1).

#define Bn   64
#define Cn   256
#define Hn   80
#define Wn   80
#define Nn   100
#define SSTR 81

__device__ __forceinline__ float gfun(const float* __restrict__ M, int y, int x)
{
    if (y == 0 || x == 0) return 0.0f;
    const int r  = y - 1;
    const int xi = x - 1;
    float v = M[r * SSTR + xi];
    if (xi >= 40) v += M[r * SSTR + 39];
    if (y >= 41) {
        v += M[39 * SSTR + xi];
        if (xi >= 40) v += M[39 * SSTR + 39];
    }
    return v;
}

__global__ __launch_bounds__(256)
void roi_pool_v10_kernel(const float* __restrict__ fmap,
                         const float* __restrict__ boxes,
                         float* __restrict__ out)
{
    __shared__ float M[Hn * SSTR];       // 25,920 B
    __shared__ int4  BC[Nn];

    const int p   = blockIdx.x;          // plane id = b*Cn + c
    const int b   = p >> 8;
    const int c   = p & 255;
    const int tid = threadIdx.x;

    const float* __restrict__ plane = fmap + (size_t)p * (Hn * Wn);

    // ---- Box coords first (their LDG overlaps the stage-in below) --------
    if (tid < Nn) {
        float4 bb = reinterpret_cast<const float4*>(boxes + (size_t)b * (Nn * 4))[tid];
        // Match JAX exactly: IEEE div by 640, IEEE mul by 80, trunc, clip.
        int x1 = min(max((int)(__fmul_rn(__fdiv_rn(bb.x, 640.0f), 80.0f)), 0), Wn);
        int y1 = min(max((int)(__fmul_rn(__fdiv_rn(bb.y, 640.0f), 80.0f)), 0), Hn);
        int x2 = min(max((int)(__fmul_rn(__fdiv_rn(bb.z, 640.0f), 80.0f)), 0), Wn);
        int y2 = min(max((int)(__fmul_rn(__fdiv_rn(bb.w, 640.0f), 80.0f)), 0), Hn);
        BC[tid] = make_int4(x1, y1, x2, y2);
    }

    // ---- Stage-in: scalar, coalesced LDG, conflict-free STS --------------
    // dst word = row*81 + x = idx + idx/80 : consecutive lanes -> consecutive
    // words (with a harmless +1 skip at row ends).
    #pragma unroll
    for (int j = 0; j < (Hn * Wn) / 256; ++j) {   // 25 iterations
        const int idx = tid + 256 * j;
        M[idx + idx / Wn] = plane[idx];
    }
    __syncthreads();

    // ---- Column scan: 160 threads, (col, seg), 40-deep, stride 81 --------
    // Lanes are consecutive columns -> consecutive words: conflict-free.
    if (tid < 160) {
        const int col  = (tid < Wn) ? tid : tid - Wn;
        const int rowb = (tid < Wn) ? 0 : 40;
        float* d = M + rowb * SSTR + col;
        float acc = 0.0f;
        #pragma unroll 8
        for (int i = 0; i < 40; ++i) {
            acc += d[i * SSTR];
            d[i * SSTR] = acc;
        }
    }
    __syncthreads();

    // ---- Row scan: 160 threads, (row, half), 40-wide, serial carry -------
    // Lanes are consecutive rows at stride 81 (odd): conflict-free.
    if (tid < 160) {
        const int r = (tid < Hn) ? tid : tid - Hn;
        const int h = (tid < Hn) ? 0 : 1;
        float* d = M + r * SSTR + 40 * h;
        float acc = 0.0f;
        #pragma unroll 8
        for (int i = 0; i < 40; ++i) {
            acc += d[i];
            d[i] = acc;
        }
    }
    __syncthreads();

    // ---- Box phase: O(1) per box (<=16 scalar LDS) -----------------------
    if (tid < Nn) {
        int4 q = BC[tid];                // x1,y1,x2,y2
        float s = gfun(M, q.w, q.z) - gfun(M, q.y, q.z)
                - gfun(M, q.w, q.x) + gfun(M, q.y, q.x);

        int dy = q.w - q.y;
        int dx = q.z - q.x;
        bool valid = (dy > 0) && (dx > 0);
        int  area  = max(dy * dx, 1);

        out[(size_t)b * (Nn * Cn) + (size_t)tid * Cn + c] =
            valid ? s / (float)area : 0.0f;
    }
}

extern "C" void kernel_launch(void* const* d_in, const int* in_sizes, int n_in,
                              void* d_out, int out_size)
{
    const float* fmap  = (const float*)d_in[0];   // [64,256,80,80]
    const float* boxes = (const float*)d_in[1];   // [64,100,4]
    float*       out   = (float*)d_out;           // [64,100,256]

    (void)in_sizes; (void)n_in; (void)out_size;

    roi_pool_v10_kernel<<<Bn * Cn, 256>>>(fmap, boxes, out);
}

// round 11
// speedup vs baseline: 1.5133x; 1.0931x over previous
#include <cuda_runtime.h>
#include <cuda_bf16.h>

// ROI mean-pool, v11: fused global-load+column-scan (no stage-in), split row
// scan, O(1) stitched-corner box phase.
//
// fmap:  [B=64, C=256, H=80, W=80] float32
// boxes: [B=64, N=100, 4] xyxy in [0,640]
// out:   [B, N, C] float32
//
// SMEM M[80][81] (odd stride -> every phase conflict-free):
//   After fused col scan: M[r][x] = column prefix (rows r<40 true, r>=40 LOCAL
//   to the lower half).
//   After row scan:       M[r][x] = x-prefix within half (x<40 | x>=40).
// 2D integral g(y,x), r=y-1, xi=x-1:
//   g = M[r][xi] + (xi>=40 ? M[r][39] : 0)
//     + (y>=41 ? M[39][xi] + (xi>=40 ? M[39][39] : 0) : 0)
// Box sum = g(y2,x2) - g(y1,x2) - g(y2,x1) + g(y1,x1).

#define Bn   64
#define Cn   256
#define Hn   80
#define Wn   80
#define Nn   100
#define SSTR 81

__device__ __forceinline__ float gfun(const float* __restrict__ M, int y, int x)
{
    if (y == 0 || x == 0) return 0.0f;
    const int r  = y - 1;
    const int xi = x - 1;
    float v = M[r * SSTR + xi];
    if (xi >= 40) v += M[r * SSTR + 39];
    if (y >= 41) {
        v += M[39 * SSTR + xi];
        if (xi >= 40) v += M[39 * SSTR + 39];
    }
    return v;
}

__global__ __launch_bounds__(256)
void roi_pool_v11_kernel(const float* __restrict__ fmap,
                         const float* __restrict__ boxes,
                         float* __restrict__ out)
{
    __shared__ float M[Hn * SSTR];       // 25,920 B
    __shared__ int4  BC[Nn];

    const int p   = blockIdx.x;          // plane id = b*Cn + c
    const int b   = p >> 8;
    const int c   = p & 255;
    const int tid = threadIdx.x;

    const float* __restrict__ plane = fmap + (size_t)p * (Hn * Wn);

    // ---- Phase 1 (one sync): fused load+col-scan | box coords ------------
    if (tid < 160) {
        // Thread (col, seg): column col, plane rows seg*40..seg*40+39.
        // Coalesced scalar LDG per iteration (lanes = consecutive columns);
        // loads are independent of the FADD carry, so they pipeline ahead.
        // Only the prefix is stored (STS, conflict-free).
        const int col  = (tid < Wn) ? tid : tid - Wn;
        const int rowb = (tid < Wn) ? 0 : 40;
        const float* __restrict__ g = plane + rowb * Wn + col;
        float*       __restrict__ d = M     + rowb * SSTR + col;

        float acc = 0.0f;
        #pragma unroll 8
        for (int i = 0; i < 40; ++i) {
            acc += g[i * Wn];
            d[i * SSTR] = acc;
        }
    } else {
        // Threads 160..255: box-coord precompute (overlapped with loads).
        const float* __restrict__ bx = boxes + (size_t)b * (Nn * 4);
        #pragma unroll
        for (int n = tid - 160; n < Nn; n += 96) {
            float4 bb = reinterpret_cast<const float4*>(bx)[n];
            // Match JAX exactly: IEEE div by 640, IEEE mul by 80, trunc, clip.
            int x1 = min(max((int)(__fmul_rn(__fdiv_rn(bb.x, 640.0f), 80.0f)), 0), Wn);
            int y1 = min(max((int)(__fmul_rn(__fdiv_rn(bb.y, 640.0f), 80.0f)), 0), Hn);
            int x2 = min(max((int)(__fmul_rn(__fdiv_rn(bb.z, 640.0f), 80.0f)), 0), Wn);
            int y2 = min(max((int)(__fmul_rn(__fdiv_rn(bb.w, 640.0f), 80.0f)), 0), Hn);
            BC[n] = make_int4(x1, y1, x2, y2);
        }
    }
    __syncthreads();

    // ---- Phase 2: row scan (160 threads, (row, half), 40-wide) -----------
    // Lanes are consecutive rows at stride 81 (odd) -> conflict-free.
    if (tid < 160) {
        const int r = (tid < Hn) ? tid : tid - Hn;
        const int h = (tid < Hn) ? 0 : 1;
        float* d = M + r * SSTR + 40 * h;
        float acc = 0.0f;
        #pragma unroll 8
        for (int i = 0; i < 40; ++i) {
            acc += d[i];
            d[i] = acc;
        }
    }
    __syncthreads();

    // ---- Phase 3: O(1) box phase (<=16 scalar LDS per box) ---------------
    if (tid < Nn) {
        int4 q = BC[tid];                // x1,y1,x2,y2
        float s = gfun(M, q.w, q.z) - gfun(M, q.y, q.z)
                - gfun(M, q.w, q.x) + gfun(M, q.y, q.x);

        int dy = q.w - q.y;
        int dx = q.z - q.x;
        bool valid = (dy > 0) && (dx > 0);
        int  area  = max(dy * dx, 1);

        out[(size_t)b * (Nn * Cn) + (size_t)tid * Cn + c] =
            valid ? s / (float)area : 0.0f;
    }
}

extern "C" void kernel_launch(void* const* d_in, const int* in_sizes, int n_in,
                              void* d_out, int out_size)
{
    const float* fmap  = (const float*)d_in[0];   // [64,256,80,80]
    const float* boxes = (const float*)d_in[1];   // [64,100,4]
    float*       out   = (float*)d_out;           // [64,100,256]

    (void)in_sizes; (void)n_in; (void)out_size;

    roi_pool_v11_kernel<<<Bn * Cn, 256>>>(fmap, boxes, out);
}